// round 2
// baseline (speedup 1.0000x reference)
#include <cuda_runtime.h>
#include <cuda_bf16.h>
#include <math.h>

// Problem constants
#define S_LEN 2048
#define HID   2048
#define NH    16
#define DN    128
#define DR    64
#define DV    128
#define DQ    192      // DN + DR
#define QLR   1536
#define KVLR  512
#define QDIM  (NH * DQ)        // 3072
#define KVDIM (NH * (DN + DV)) // 4096
#define AODIM (NH * DV)        // 2048
#define SCALE 0.07216878364870323f  // 192^-0.5
#define EPSV  1e-6f

// ---------------- scratch (allocation-free: __device__ global) ----------------
#define OFF_QA    0UL
#define OFF_Q     (OFF_QA   + (size_t)S_LEN * QLR)     //  3,145,728
#define OFF_CKV   (OFF_Q    + (size_t)S_LEN * QDIM)
#define OFF_CKVN  (OFF_CKV  + (size_t)S_LEN * 576)
#define OFF_KPE   (OFF_CKVN + (size_t)S_LEN * KVLR)
#define OFF_KV    (OFF_KPE  + (size_t)S_LEN * DR)
#define OFF_ATTN  (OFF_KV   + (size_t)S_LEN * KVDIM)
#define SCRATCH_TOTAL (OFF_ATTN + (size_t)S_LEN * AODIM)

__device__ float g_scratch[SCRATCH_TOTAL];

// ---------------- GEMM: C[M,N] = A[M,K] * W[N,K]^T (all row-major, K contiguous)
// BM=128, BN=64, BK=16, 256 threads, 8x4 micro-tile.
__global__ __launch_bounds__(256) void gemm_abt(
    const float* __restrict__ A, const float* __restrict__ W,
    float* __restrict__ C, int M, int N, int K)
{
    __shared__ float As[16][129];
    __shared__ float Ws[16][65];

    const int t  = threadIdx.x;
    const int m0 = blockIdx.y * 128;
    const int n0 = blockIdx.x * 64;
    const int ty = t >> 4;       // 0..15  -> 8 rows each
    const int tx = t & 15;       // 0..15  -> 4 cols each

    float acc[8][4];
#pragma unroll
    for (int i = 0; i < 8; i++)
#pragma unroll
        for (int j = 0; j < 4; j++) acc[i][j] = 0.f;

    const int lr = t >> 2;            // 0..63
    const int lc = (t & 3) << 2;      // 0,4,8,12
    const float* Ap0 = A + (size_t)(m0 + lr) * K + lc;
    const float* Ap1 = Ap0 + (size_t)64 * K;
    const float* Wp  = W + (size_t)(n0 + lr) * K + lc;

    for (int k0 = 0; k0 < K; k0 += 16) {
        float4 a0 = *(const float4*)(Ap0 + k0);
        float4 a1 = *(const float4*)(Ap1 + k0);
        float4 wv = *(const float4*)(Wp + k0);
        As[lc + 0][lr]      = a0.x; As[lc + 1][lr]      = a0.y;
        As[lc + 2][lr]      = a0.z; As[lc + 3][lr]      = a0.w;
        As[lc + 0][lr + 64] = a1.x; As[lc + 1][lr + 64] = a1.y;
        As[lc + 2][lr + 64] = a1.z; As[lc + 3][lr + 64] = a1.w;
        Ws[lc + 0][lr] = wv.x; Ws[lc + 1][lr] = wv.y;
        Ws[lc + 2][lr] = wv.z; Ws[lc + 3][lr] = wv.w;
        __syncthreads();
#pragma unroll
        for (int kk = 0; kk < 16; kk++) {
            float a[8], b[4];
#pragma unroll
            for (int i = 0; i < 8; i++) a[i] = As[kk][ty * 8 + i];
#pragma unroll
            for (int j = 0; j < 4; j++) b[j] = Ws[kk][tx * 4 + j];
#pragma unroll
            for (int i = 0; i < 8; i++)
#pragma unroll
                for (int j = 0; j < 4; j++) acc[i][j] = fmaf(a[i], b[j], acc[i][j]);
        }
        __syncthreads();
    }

#pragma unroll
    for (int i = 0; i < 8; i++) {
        float4 v = make_float4(acc[i][0], acc[i][1], acc[i][2], acc[i][3]);
        *(float4*)(C + (size_t)(m0 + ty * 8 + i) * N + n0 + tx * 4) = v;
    }
}

// ---------------- RMSNorm: per-row, y = x * rsqrt(mean(x^2)+eps) * w ----------
__global__ __launch_bounds__(256) void rmsnorm_kernel(
    const float* __restrict__ X, int ldx, const float* __restrict__ w,
    float* __restrict__ Y, int ldy, int n)
{
    const int row = blockIdx.x;
    const float* x = X + (size_t)row * ldx;
    float* y = Y + (size_t)row * ldy;

    float s = 0.f;
    for (int i = threadIdx.x; i < n; i += blockDim.x) { float v = x[i]; s += v * v; }

    __shared__ float red[8];
    int lane = threadIdx.x & 31, wid = threadIdx.x >> 5;
#pragma unroll
    for (int o = 16; o; o >>= 1) s += __shfl_down_sync(0xFFFFFFFFu, s, o);
    if (!lane) red[wid] = s;
    __syncthreads();
    if (wid == 0) {
        s = (lane < 8) ? red[lane] : 0.f;
#pragma unroll
        for (int o = 4; o; o >>= 1) s += __shfl_down_sync(0xFFFFFFFFu, s, o);
        if (!lane) red[0] = s;
    }
    __syncthreads();
    const float inv = rsqrtf(red[0] / (float)n + EPSV);
    for (int i = threadIdx.x; i < n; i += blockDim.x) y[i] = x[i] * inv * w[i];
}

// ---------------- k_pe RoPE: ckv[:,512:576] -> kpe[S,64] ----------------------
__global__ __launch_bounds__(256) void kpe_rope_kernel(
    const float* __restrict__ ckv, const int* __restrict__ pos,
    const float* __restrict__ cosb, const float* __restrict__ sinb,
    float* __restrict__ kpe)
{
    int warp = (blockIdx.x * blockDim.x + threadIdx.x) >> 5;
    int lane = threadIdx.x & 31;
    if (warp >= S_LEN) return;
    int s = warp;
    int p = pos[s];
    const float* x = ckv + (size_t)s * 576 + 512;
    float x0 = x[2 * lane], x1 = x[2 * lane + 1];
    float c0 = cosb[(size_t)p * DR + lane],      s0 = sinb[(size_t)p * DR + lane];
    float c1 = cosb[(size_t)p * DR + 32 + lane], s1 = sinb[(size_t)p * DR + 32 + lane];
    kpe[(size_t)s * DR + lane]      = x0 * c0 - x1 * s0;
    kpe[(size_t)s * DR + 32 + lane] = x1 * c1 + x0 * s1;
}

// ---------------- q_pe RoPE (in place): Q[s, h*192+128 .. +64] ----------------
__global__ __launch_bounds__(256) void q_rope_kernel(
    float* __restrict__ Q, const int* __restrict__ pos,
    const float* __restrict__ cosb, const float* __restrict__ sinb)
{
    int warp = (blockIdx.x * blockDim.x + threadIdx.x) >> 5;
    int lane = threadIdx.x & 31;
    if (warp >= S_LEN * NH) return;
    int s = warp >> 4, h = warp & 15;
    int p = pos[s];
    float* x = Q + (size_t)s * QDIM + h * DQ + DN;
    float x0 = x[2 * lane], x1 = x[2 * lane + 1];
    float c0 = cosb[(size_t)p * DR + lane],      s0 = sinb[(size_t)p * DR + lane];
    float c1 = cosb[(size_t)p * DR + 32 + lane], s1 = sinb[(size_t)p * DR + 32 + lane];
    float o0 = x0 * c0 - x1 * s0;
    float o1 = x1 * c1 + x0 * s1;
    __syncwarp();
    x[lane]      = o0;
    x[32 + lane] = o1;
}

// ---------------- Flash attention (causal, fp32) ------------------------------
// Grid (32, 16): x = q-block (reversed for load balance), y = head.
// 256 threads. smem: Qs[64][193], Ks[64][193], Vs[64][128], Ps[64][65], stats.
#define SD 193
#define ATT_SMEM_FLOATS (2 * 64 * SD + 64 * 128 + 64 * 65 + 3 * 64)

__global__ __launch_bounds__(256) void attn_kernel(
    const float* __restrict__ Q, const float* __restrict__ KV,
    const float* __restrict__ KPE, float* __restrict__ O)
{
    extern __shared__ float sm[];
    float* Qs   = sm;                   // [64][SD]
    float* Ks   = Qs + 64 * SD;         // [64][SD]
    float* Vs   = Ks + 64 * SD;         // [64][128]
    float* Ps   = Vs + 64 * 128;        // [64][65]
    float* mrow = Ps + 64 * 65;
    float* lrow = mrow + 64;
    float* arow = lrow + 64;

    const int h  = blockIdx.y;
    const int qb = 31 - blockIdx.x;     // big blocks first
    const int q0 = qb * 64;
    const int t  = threadIdx.x;
    const int ty = t >> 4, tx = t & 15;

    // load Q tile [64 x 192]
    for (int idx = t; idx < 64 * 48; idx += 256) {
        int r = idx / 48, c4 = (idx % 48) * 4;
        float4 v = *(const float4*)(Q + (size_t)(q0 + r) * QDIM + h * DQ + c4);
        Qs[r * SD + c4 + 0] = v.x; Qs[r * SD + c4 + 1] = v.y;
        Qs[r * SD + c4 + 2] = v.z; Qs[r * SD + c4 + 3] = v.w;
    }
    if (t < 64) { mrow[t] = -1e30f; lrow[t] = 0.f; }

    float o[4][8];
#pragma unroll
    for (int i = 0; i < 4; i++)
#pragma unroll
        for (int j = 0; j < 8; j++) o[i][j] = 0.f;
    __syncthreads();

    for (int kt = 0; kt <= qb; kt++) {
        const int k0 = kt * 64;
        // load K tile [64 x 192]: 0..127 from kv (k_nope), 128..191 from kpe
        for (int idx = t; idx < 64 * 48; idx += 256) {
            int r = idx / 48, c4 = (idx % 48) * 4;
            float4 v;
            if (c4 < 128) v = *(const float4*)(KV  + (size_t)(k0 + r) * KVDIM + h * 256 + c4);
            else          v = *(const float4*)(KPE + (size_t)(k0 + r) * DR + (c4 - 128));
            Ks[r * SD + c4 + 0] = v.x; Ks[r * SD + c4 + 1] = v.y;
            Ks[r * SD + c4 + 2] = v.z; Ks[r * SD + c4 + 3] = v.w;
        }
        // load V tile [64 x 128]
        for (int idx = t; idx < 64 * 32; idx += 256) {
            int r = idx >> 5, c4 = (idx & 31) * 4;
            *(float4*)(Vs + r * 128 + c4) =
                *(const float4*)(KV + (size_t)(k0 + r) * KVDIM + h * 256 + 128 + c4);
        }
        __syncthreads();

        // S = Q K^T (64x64), 4x4 per thread
        float sacc[4][4];
#pragma unroll
        for (int i = 0; i < 4; i++)
#pragma unroll
            for (int j = 0; j < 4; j++) sacc[i][j] = 0.f;
        for (int d = 0; d < 192; d++) {
            float a[4], b[4];
#pragma unroll
            for (int i = 0; i < 4; i++) a[i] = Qs[(ty * 4 + i) * SD + d];
#pragma unroll
            for (int j = 0; j < 4; j++) b[j] = Ks[(tx * 4 + j) * SD + d];
#pragma unroll
            for (int i = 0; i < 4; i++)
#pragma unroll
                for (int j = 0; j < 4; j++) sacc[i][j] = fmaf(a[i], b[j], sacc[i][j]);
        }
        const bool diag = (kt == qb);
#pragma unroll
        for (int i = 0; i < 4; i++)
#pragma unroll
            for (int j = 0; j < 4; j++) {
                float v = sacc[i][j] * SCALE;
                if (diag && (k0 + tx * 4 + j) > (q0 + ty * 4 + i)) v = -1e30f;
                Ps[(ty * 4 + i) * 65 + tx * 4 + j] = v;
            }
        __syncthreads();

        // online softmax per row (threads 0..63)
        if (t < 64) {
            float mprev = mrow[t], mx = mprev;
#pragma unroll 8
            for (int c = 0; c < 64; c++) mx = fmaxf(mx, Ps[t * 65 + c]);
            float al = __expf(mprev - mx);
            float ls = lrow[t] * al;
#pragma unroll 8
            for (int c = 0; c < 64; c++) {
                float e = __expf(Ps[t * 65 + c] - mx);
                Ps[t * 65 + c] = e;
                ls += e;
            }
            mrow[t] = mx; lrow[t] = ls; arow[t] = al;
        }
        __syncthreads();

        // O = O*alpha + P @ V
        float al[4];
#pragma unroll
        for (int i = 0; i < 4; i++) al[i] = arow[ty * 4 + i];
#pragma unroll
        for (int i = 0; i < 4; i++)
#pragma unroll
            for (int j = 0; j < 8; j++) o[i][j] *= al[i];
        for (int kk = 0; kk < 64; kk++) {
            float p[4];
#pragma unroll
            for (int i = 0; i < 4; i++) p[i] = Ps[(ty * 4 + i) * 65 + kk];
            float4 v0 = *(float4*)(Vs + kk * 128 + tx * 8);
            float4 v1 = *(float4*)(Vs + kk * 128 + tx * 8 + 4);
            float vv[8] = {v0.x, v0.y, v0.z, v0.w, v1.x, v1.y, v1.z, v1.w};
#pragma unroll
            for (int i = 0; i < 4; i++)
#pragma unroll
                for (int j = 0; j < 8; j++) o[i][j] = fmaf(p[i], vv[j], o[i][j]);
        }
        __syncthreads();
    }

    // normalize and store
#pragma unroll
    for (int i = 0; i < 4; i++) {
        float inv = 1.f / lrow[ty * 4 + i];
        float4 u0 = make_float4(o[i][0] * inv, o[i][1] * inv, o[i][2] * inv, o[i][3] * inv);
        float4 u1 = make_float4(o[i][4] * inv, o[i][5] * inv, o[i][6] * inv, o[i][7] * inv);
        float* dst = O + (size_t)(q0 + ty * 4 + i) * AODIM + h * DV + tx * 8;
        *(float4*)(dst)     = u0;
        *(float4*)(dst + 4) = u1;
    }
}

// ---------------- host launcher ----------------------------------------------
static inline void launch_gemm(const float* A, const float* W, float* C,
                               int M, int N, int K) {
    dim3 grid(N / 64, M / 128);
    gemm_abt<<<grid, 256>>>(A, W, C, M, N, K);
}

extern "C" void kernel_launch(void* const* d_in, const int* in_sizes, int n_in,
                              void* d_out, int out_size)
{
    const float* hidden  = (const float*)d_in[0];
    const float* q_a_w   = (const float*)d_in[1];
    const float* q_a_ln  = (const float*)d_in[2];
    const float* q_b_w   = (const float*)d_in[3];
    const float* kv_a_w  = (const float*)d_in[4];
    const float* kv_a_ln = (const float*)d_in[5];
    const float* kv_b_w  = (const float*)d_in[6];
    const float* o_w     = (const float*)d_in[7];
    const float* cosb    = (const float*)d_in[8];
    const float* sinb    = (const float*)d_in[9];
    // d_in[10] = attention_mask (causal triu; semantics reproduced directly)
    const int*   pos     = (const int*)d_in[11];
    float* out = (float*)d_out;

    float* base;
    cudaGetSymbolAddress((void**)&base, g_scratch);
    float* qa   = base + OFF_QA;
    float* q    = base + OFF_Q;
    float* ckv  = base + OFF_CKV;
    float* ckvn = base + OFF_CKVN;
    float* kpe  = base + OFF_KPE;
    float* kv   = base + OFF_KV;
    float* attn = base + OFF_ATTN;

    const int att_smem = ATT_SMEM_FLOATS * (int)sizeof(float);
    cudaFuncSetAttribute(attn_kernel, cudaFuncAttributeMaxDynamicSharedMemorySize, att_smem);

    // 1) q_a = hidden @ q_a_w^T           [2048,1536]
    launch_gemm(hidden, q_a_w, qa, S_LEN, QLR, HID);
    // 2) ckv = hidden @ kv_a_w^T          [2048,576]
    launch_gemm(hidden, kv_a_w, ckv, S_LEN, 576, HID);
    // 3) rmsnorm(q_a) in place
    rmsnorm_kernel<<<S_LEN, 256>>>(qa, QLR, q_a_ln, qa, QLR, QLR);
    // 4) rmsnorm(ckv[:, :512]) -> ckvn
    rmsnorm_kernel<<<S_LEN, 256>>>(ckv, 576, kv_a_ln, ckvn, KVLR, KVLR);
    // 5) rope(k_pe) -> kpe
    kpe_rope_kernel<<<(S_LEN * 32 + 255) / 256, 256>>>(ckv, pos, cosb, sinb, kpe);
    // 6) q = qa_n @ q_b_w^T               [2048,3072]
    launch_gemm(qa, q_b_w, q, S_LEN, QDIM, QLR);
    // 7) kv = ckvn @ kv_b_w^T             [2048,4096]
    launch_gemm(ckvn, kv_b_w, kv, S_LEN, KVDIM, KVLR);
    // 8) rope(q_pe) in place
    q_rope_kernel<<<(S_LEN * NH * 32 + 255) / 256, 256>>>(q, pos, cosb, sinb);
    // 9) attention -> attn                [2048,2048]
    attn_kernel<<<dim3(32, NH), 256, att_smem>>>(q, kv, kpe, attn);
    // 10) out = attn @ o_w^T              [2048,2048]
    launch_gemm(attn, o_w, out, S_LEN, HID, AODIM);
}

// round 3
// speedup vs baseline: 2.3250x; 2.3250x over previous
#include <cuda_runtime.h>
#include <cuda_bf16.h>
#include <math.h>

// Problem constants
#define S_LEN 2048
#define HID   2048
#define NH    16
#define DN    128
#define DR    64
#define DV    128
#define DQ    192      // DN + DR
#define QLR   1536
#define KVLR  512
#define QDIM  (NH * DQ)        // 3072
#define KVDIM (NH * (DN + DV)) // 4096
#define AODIM (NH * DV)        // 2048
#define SCALE 0.07216878364870323f  // 192^-0.5
#define EPSV  1e-6f

// ---------------- scratch (allocation-free: __device__ global) ----------------
#define OFF_QA    0UL
#define OFF_Q     (OFF_QA   + (size_t)S_LEN * QLR)
#define OFF_CKV   (OFF_Q    + (size_t)S_LEN * QDIM)
#define OFF_CKVN  (OFF_CKV  + (size_t)S_LEN * 576)
#define OFF_KPE   (OFF_CKVN + (size_t)S_LEN * KVLR)
#define OFF_KV    (OFF_KPE  + (size_t)S_LEN * DR)
#define OFF_ATTN  (OFF_KV   + (size_t)S_LEN * KVDIM)
#define SCRATCH_TOTAL (OFF_ATTN + (size_t)S_LEN * AODIM)

__device__ float g_scratch[SCRATCH_TOTAL];

// ---------------- helpers ------------------------------------------------------
__device__ __forceinline__ unsigned f2tf(float x) {
    unsigned u;
    asm("cvt.rna.tf32.f32 %0, %1;" : "=r"(u) : "f"(x));
    return u;
}

// D = A(16x8 tf32, row) * B(8x8 tf32, col) + D, fp32 accum
__device__ __forceinline__ void mma8(float* d, const unsigned* a, const unsigned* b) {
    asm volatile(
        "mma.sync.aligned.m16n8k8.row.col.f32.tf32.tf32.f32 "
        "{%0,%1,%2,%3},{%4,%5,%6,%7},{%8,%9},{%0,%1,%2,%3};\n"
        : "+f"(d[0]), "+f"(d[1]), "+f"(d[2]), "+f"(d[3])
        : "r"(a[0]), "r"(a[1]), "r"(a[2]), "r"(a[3]), "r"(b[0]), "r"(b[1]));
}

// ---------------- GEMM: C[M,N] = A[M,K] * W[N,K]^T, tf32 tensor cores ----------
// BM=128, BN=128, BK=16, 256 threads (8 warps, 4x2), warp tile 32x64.
#define GS 20  // smem row stride (k), 20 % 8 == 4 -> conflict-free fragment LDS

__global__ __launch_bounds__(256) void gemm_tf32(
    const float* __restrict__ A, const float* __restrict__ W,
    float* __restrict__ C, int M, int N, int K)
{
    __shared__ unsigned As[128 * GS];
    __shared__ unsigned Bs[128 * GS];

    const int t    = threadIdx.x;
    const int lane = t & 31;
    const int wid  = t >> 5;
    const int ln4  = lane >> 2;   // 0..7
    const int lnk  = lane & 3;    // 0..3
    const int warpM = wid & 3;    // 0..3 -> 32 rows
    const int warpN = wid >> 2;   // 0..1 -> 64 cols
    const int m0 = blockIdx.y * 128;
    const int n0 = blockIdx.x * 128;

    const int lr = t >> 2;        // 0..63
    const int lc = (t & 3) * 4;   // 0,4,8,12

    float acc[2][8][4];
#pragma unroll
    for (int mt = 0; mt < 2; mt++)
#pragma unroll
        for (int nt = 0; nt < 8; nt++)
#pragma unroll
            for (int j = 0; j < 4; j++) acc[mt][nt][j] = 0.f;

    for (int k0 = 0; k0 < K; k0 += 16) {
#pragma unroll
        for (int half = 0; half < 2; half++) {
            int r = lr + half * 64;
            float4 va = *(const float4*)(A + (size_t)(m0 + r) * K + k0 + lc);
            As[r * GS + lc + 0] = f2tf(va.x);
            As[r * GS + lc + 1] = f2tf(va.y);
            As[r * GS + lc + 2] = f2tf(va.z);
            As[r * GS + lc + 3] = f2tf(va.w);
            int nrow = n0 + r;
            float4 vw = make_float4(0.f, 0.f, 0.f, 0.f);
            if (nrow < N) vw = *(const float4*)(W + (size_t)nrow * K + k0 + lc);
            Bs[r * GS + lc + 0] = f2tf(vw.x);
            Bs[r * GS + lc + 1] = f2tf(vw.y);
            Bs[r * GS + lc + 2] = f2tf(vw.z);
            Bs[r * GS + lc + 3] = f2tf(vw.w);
        }
        __syncthreads();

#pragma unroll
        for (int ks = 0; ks < 2; ks++) {
            const int kk = ks * 8;
            unsigned a[2][4], b[8][2];
#pragma unroll
            for (int mt = 0; mt < 2; mt++) {
                const unsigned* p = As + (warpM * 32 + mt * 16 + ln4) * GS + kk + lnk;
                a[mt][0] = p[0];
                a[mt][1] = p[8 * GS];
                a[mt][2] = p[4];
                a[mt][3] = p[8 * GS + 4];
            }
#pragma unroll
            for (int nt = 0; nt < 8; nt++) {
                const unsigned* p = Bs + (warpN * 64 + nt * 8 + ln4) * GS + kk + lnk;
                b[nt][0] = p[0];
                b[nt][1] = p[4];
            }
#pragma unroll
            for (int mt = 0; mt < 2; mt++)
#pragma unroll
                for (int nt = 0; nt < 8; nt++) mma8(acc[mt][nt], a[mt], b[nt]);
        }
        __syncthreads();
    }

#pragma unroll
    for (int mt = 0; mt < 2; mt++) {
        int r0 = m0 + warpM * 32 + mt * 16 + ln4;
#pragma unroll
        for (int nt = 0; nt < 8; nt++) {
            int c = n0 + warpN * 64 + nt * 8 + 2 * lnk;
            if (c < N) {
                *(float2*)(C + (size_t)r0 * N + c)       = make_float2(acc[mt][nt][0], acc[mt][nt][1]);
                *(float2*)(C + (size_t)(r0 + 8) * N + c) = make_float2(acc[mt][nt][2], acc[mt][nt][3]);
            }
        }
    }
}

// ---------------- RMSNorm ------------------------------------------------------
__global__ __launch_bounds__(256) void rmsnorm_kernel(
    const float* __restrict__ X, int ldx, const float* __restrict__ w,
    float* __restrict__ Y, int ldy, int n)
{
    const int row = blockIdx.x;
    const float* x = X + (size_t)row * ldx;
    float* y = Y + (size_t)row * ldy;

    float s = 0.f;
    for (int i = threadIdx.x; i < n; i += blockDim.x) { float v = x[i]; s += v * v; }

    __shared__ float red[8];
    int lane = threadIdx.x & 31, wid = threadIdx.x >> 5;
#pragma unroll
    for (int o = 16; o; o >>= 1) s += __shfl_down_sync(0xFFFFFFFFu, s, o);
    if (!lane) red[wid] = s;
    __syncthreads();
    if (wid == 0) {
        s = (lane < 8) ? red[lane] : 0.f;
#pragma unroll
        for (int o = 4; o; o >>= 1) s += __shfl_down_sync(0xFFFFFFFFu, s, o);
        if (!lane) red[0] = s;
    }
    __syncthreads();
    const float inv = rsqrtf(red[0] / (float)n + EPSV);
    for (int i = threadIdx.x; i < n; i += blockDim.x) y[i] = x[i] * inv * w[i];
}

// ---------------- k_pe RoPE ----------------------------------------------------
__global__ __launch_bounds__(256) void kpe_rope_kernel(
    const float* __restrict__ ckv, const int* __restrict__ pos,
    const float* __restrict__ cosb, const float* __restrict__ sinb,
    float* __restrict__ kpe)
{
    int warp = (blockIdx.x * blockDim.x + threadIdx.x) >> 5;
    int lane = threadIdx.x & 31;
    if (warp >= S_LEN) return;
    int s = warp;
    int p = pos[s];
    const float* x = ckv + (size_t)s * 576 + 512;
    float x0 = x[2 * lane], x1 = x[2 * lane + 1];
    float c0 = cosb[(size_t)p * DR + lane],      s0 = sinb[(size_t)p * DR + lane];
    float c1 = cosb[(size_t)p * DR + 32 + lane], s1 = sinb[(size_t)p * DR + 32 + lane];
    kpe[(size_t)s * DR + lane]      = x0 * c0 - x1 * s0;
    kpe[(size_t)s * DR + 32 + lane] = x1 * c1 + x0 * s1;
}

// ---------------- q_pe RoPE (in place) -----------------------------------------
__global__ __launch_bounds__(256) void q_rope_kernel(
    float* __restrict__ Q, const int* __restrict__ pos,
    const float* __restrict__ cosb, const float* __restrict__ sinb)
{
    int warp = (blockIdx.x * blockDim.x + threadIdx.x) >> 5;
    int lane = threadIdx.x & 31;
    if (warp >= S_LEN * NH) return;
    int s = warp >> 4, h = warp & 15;
    int p = pos[s];
    float* x = Q + (size_t)s * QDIM + h * DQ + DN;
    float x0 = x[2 * lane], x1 = x[2 * lane + 1];
    float c0 = cosb[(size_t)p * DR + lane],      s0 = sinb[(size_t)p * DR + lane];
    float c1 = cosb[(size_t)p * DR + 32 + lane], s1 = sinb[(size_t)p * DR + 32 + lane];
    float o0 = x0 * c0 - x1 * s0;
    float o1 = x1 * c1 + x0 * s1;
    __syncwarp();
    x[lane]      = o0;
    x[32 + lane] = o1;
}

// ---------------- Flash attention (causal, tf32 tensor cores) ------------------
// Grid (32, 16): x = q-block (reversed), y = head. 256 threads (8 warps).
// smem (uint/float): Qs[64][196], Ks[64][196], Vs[64][136], Ps[64][68], stats.
#define QKS 196   // 196 % 8 == 4 -> conflict-free A/B-frag (row-major, n-major) LDS
#define VS_ 136   // 136 % 16 == 8 -> conflict-free B-frag LDS for k-major V
#define PS_ 68

#define ATT_SMEM_WORDS (2 * 64 * QKS + 64 * VS_ + 64 * PS_ + 3 * 64)

__global__ __launch_bounds__(256) void attn_kernel(
    const float* __restrict__ Q, const float* __restrict__ KV,
    const float* __restrict__ KPE, float* __restrict__ O)
{
    extern __shared__ unsigned smu[];
    unsigned* Qs = smu;
    unsigned* Ks = Qs + 64 * QKS;
    unsigned* Vs = Ks + 64 * QKS;
    unsigned* Ps = Vs + 64 * VS_;
    float* mrow = (float*)(Ps + 64 * PS_);
    float* lrow = mrow + 64;
    float* arow = lrow + 64;

    const int h  = blockIdx.y;
    const int qb = 31 - blockIdx.x;     // big blocks first
    const int q0 = qb * 64;
    const int t    = threadIdx.x;
    const int lane = t & 31;
    const int wid  = t >> 5;
    const int ln4  = lane >> 2;
    const int lnk  = lane & 3;
    const int warpM = wid & 3;   // rows: 16 each (S and PV)
    const int warpN = wid >> 2;  // cols: 32 (S), 64 (PV)

    // load Q tile [64 x 192] -> tf32
    for (int idx = t; idx < 64 * 48; idx += 256) {
        int r = idx / 48, c4 = (idx % 48) * 4;
        float4 v = *(const float4*)(Q + (size_t)(q0 + r) * QDIM + h * DQ + c4);
        Qs[r * QKS + c4 + 0] = f2tf(v.x);
        Qs[r * QKS + c4 + 1] = f2tf(v.y);
        Qs[r * QKS + c4 + 2] = f2tf(v.z);
        Qs[r * QKS + c4 + 3] = f2tf(v.w);
    }
    if (t < 64) { mrow[t] = -1e30f; lrow[t] = 0.f; }

    float o[8][4];
#pragma unroll
    for (int nt = 0; nt < 8; nt++)
#pragma unroll
        for (int j = 0; j < 4; j++) o[nt][j] = 0.f;
    __syncthreads();

    for (int kt = 0; kt <= qb; kt++) {
        const int k0 = kt * 64;
        // K tile [64 x 192]: 0..127 k_nope from KV, 128..191 from KPE
        for (int idx = t; idx < 64 * 48; idx += 256) {
            int r = idx / 48, c4 = (idx % 48) * 4;
            float4 v;
            if (c4 < 128) v = *(const float4*)(KV  + (size_t)(k0 + r) * KVDIM + h * 256 + c4);
            else          v = *(const float4*)(KPE + (size_t)(k0 + r) * DR + (c4 - 128));
            Ks[r * QKS + c4 + 0] = f2tf(v.x);
            Ks[r * QKS + c4 + 1] = f2tf(v.y);
            Ks[r * QKS + c4 + 2] = f2tf(v.z);
            Ks[r * QKS + c4 + 3] = f2tf(v.w);
        }
        // V tile [64 x 128]
        for (int idx = t; idx < 64 * 32; idx += 256) {
            int r = idx >> 5, c4 = (idx & 31) * 4;
            float4 v = *(const float4*)(KV + (size_t)(k0 + r) * KVDIM + h * 256 + 128 + c4);
            Vs[r * VS_ + c4 + 0] = f2tf(v.x);
            Vs[r * VS_ + c4 + 1] = f2tf(v.y);
            Vs[r * VS_ + c4 + 2] = f2tf(v.z);
            Vs[r * VS_ + c4 + 3] = f2tf(v.w);
        }
        __syncthreads();

        // ---- S = Q K^T (64x64), warp tile 16x32 (4 n-tiles), k = 192 ----
        float sacc[4][4];
#pragma unroll
        for (int nt = 0; nt < 4; nt++)
#pragma unroll
            for (int j = 0; j < 4; j++) sacc[nt][j] = 0.f;

        const unsigned* qbase = Qs + (warpM * 16 + ln4) * QKS + lnk;
#pragma unroll 4
        for (int ks = 0; ks < 24; ks++) {
            const int kk = ks * 8;
            unsigned a[4];
            a[0] = qbase[kk];
            a[1] = qbase[8 * QKS + kk];
            a[2] = qbase[kk + 4];
            a[3] = qbase[8 * QKS + kk + 4];
#pragma unroll
            for (int nt = 0; nt < 4; nt++) {
                const unsigned* p = Ks + (warpN * 32 + nt * 8 + ln4) * QKS + kk + lnk;
                unsigned b[2] = { p[0], p[4] };
                mma8(sacc[nt], a, b);
            }
        }

        // scale + mask, store raw float to Ps
        const bool diag = (kt == qb);
        const int rl0 = warpM * 16 + ln4;   // local rows rl0, rl0+8
#pragma unroll
        for (int nt = 0; nt < 4; nt++) {
            int cl = warpN * 32 + nt * 8 + 2 * lnk;
            float v0 = sacc[nt][0] * SCALE;
            float v1 = sacc[nt][1] * SCALE;
            float v2 = sacc[nt][2] * SCALE;
            float v3 = sacc[nt][3] * SCALE;
            if (diag) {
                if (cl     > rl0)     v0 = -1e30f;
                if (cl + 1 > rl0)     v1 = -1e30f;
                if (cl     > rl0 + 8) v2 = -1e30f;
                if (cl + 1 > rl0 + 8) v3 = -1e30f;
            }
            Ps[rl0 * PS_ + cl]           = __float_as_uint(v0);
            Ps[rl0 * PS_ + cl + 1]       = __float_as_uint(v1);
            Ps[(rl0 + 8) * PS_ + cl]     = __float_as_uint(v2);
            Ps[(rl0 + 8) * PS_ + cl + 1] = __float_as_uint(v3);
        }
        __syncthreads();

        // ---- online softmax: 4 threads per row, 16 cols each ----
        {
            const int r = t >> 2, seg = t & 3;
            const float* pf = (const float*)Ps + r * PS_ + seg * 16;
            unsigned* pu = Ps + r * PS_ + seg * 16;
            float mprev = mrow[r];
            float mx = mprev;
#pragma unroll
            for (int j = 0; j < 16; j++) mx = fmaxf(mx, pf[j]);
            mx = fmaxf(mx, __shfl_xor_sync(0xFFFFFFFFu, mx, 1));
            mx = fmaxf(mx, __shfl_xor_sync(0xFFFFFFFFu, mx, 2));
            float alpha = __expf(mprev - mx);
            float s = 0.f;
#pragma unroll
            for (int j = 0; j < 16; j++) {
                float e = __expf(pf[j] - mx);
                s += e;
                pu[j] = f2tf(e);
            }
            s += __shfl_xor_sync(0xFFFFFFFFu, s, 1);
            s += __shfl_xor_sync(0xFFFFFFFFu, s, 2);
            if (seg == 0) {
                mrow[r] = mx;
                lrow[r] = lrow[r] * alpha + s;
                arow[r] = alpha;
            }
        }
        __syncthreads();

        // ---- O = O*alpha + P @ V, warp tile 16x64 (8 n-tiles), k = 64 ----
        {
            float ar0 = arow[warpM * 16 + ln4];
            float ar1 = arow[warpM * 16 + ln4 + 8];
#pragma unroll
            for (int nt = 0; nt < 8; nt++) {
                o[nt][0] *= ar0; o[nt][1] *= ar0;
                o[nt][2] *= ar1; o[nt][3] *= ar1;
            }
            const unsigned* pbase = Ps + (warpM * 16 + ln4) * PS_ + lnk;
#pragma unroll
            for (int ks = 0; ks < 8; ks++) {
                const int kk = ks * 8;
                unsigned a[4];
                a[0] = pbase[kk];
                a[1] = pbase[8 * PS_ + kk];
                a[2] = pbase[kk + 4];
                a[3] = pbase[8 * PS_ + kk + 4];
#pragma unroll
                for (int nt = 0; nt < 8; nt++) {
                    const unsigned* p = Vs + (kk + lnk) * VS_ + warpN * 64 + nt * 8 + ln4;
                    unsigned b[2] = { p[0], p[4 * VS_] };
                    mma8(o[nt], a, b);
                }
            }
        }
        __syncthreads();
    }

    // normalize and store
    {
        float inv0 = 1.f / lrow[warpM * 16 + ln4];
        float inv1 = 1.f / lrow[warpM * 16 + ln4 + 8];
        int r0 = q0 + warpM * 16 + ln4;
#pragma unroll
        for (int nt = 0; nt < 8; nt++) {
            int c = warpN * 64 + nt * 8 + 2 * lnk;
            float* dst0 = O + (size_t)r0 * AODIM + h * DV + c;
            float* dst1 = O + (size_t)(r0 + 8) * AODIM + h * DV + c;
            *(float2*)dst0 = make_float2(o[nt][0] * inv0, o[nt][1] * inv0);
            *(float2*)dst1 = make_float2(o[nt][2] * inv1, o[nt][3] * inv1);
        }
    }
}

// ---------------- host launcher -------------------------------------------------
static inline void launch_gemm(const float* A, const float* W, float* C,
                               int M, int N, int K) {
    dim3 grid((N + 127) / 128, M / 128);
    gemm_tf32<<<grid, 256>>>(A, W, C, M, N, K);
}

extern "C" void kernel_launch(void* const* d_in, const int* in_sizes, int n_in,
                              void* d_out, int out_size)
{
    const float* hidden  = (const float*)d_in[0];
    const float* q_a_w   = (const float*)d_in[1];
    const float* q_a_ln  = (const float*)d_in[2];
    const float* q_b_w   = (const float*)d_in[3];
    const float* kv_a_w  = (const float*)d_in[4];
    const float* kv_a_ln = (const float*)d_in[5];
    const float* kv_b_w  = (const float*)d_in[6];
    const float* o_w     = (const float*)d_in[7];
    const float* cosb    = (const float*)d_in[8];
    const float* sinb    = (const float*)d_in[9];
    // d_in[10] = attention_mask (causal triu; semantics reproduced directly)
    const int*   pos     = (const int*)d_in[11];
    float* out = (float*)d_out;

    float* base;
    cudaGetSymbolAddress((void**)&base, g_scratch);
    float* qa   = base + OFF_QA;
    float* q    = base + OFF_Q;
    float* ckv  = base + OFF_CKV;
    float* ckvn = base + OFF_CKVN;
    float* kpe  = base + OFF_KPE;
    float* kv   = base + OFF_KV;
    float* attn = base + OFF_ATTN;

    const int att_smem = ATT_SMEM_WORDS * 4;
    cudaFuncSetAttribute(attn_kernel, cudaFuncAttributeMaxDynamicSharedMemorySize, att_smem);

    // 1) q_a = hidden @ q_a_w^T           [2048,1536]
    launch_gemm(hidden, q_a_w, qa, S_LEN, QLR, HID);
    // 2) ckv = hidden @ kv_a_w^T          [2048,576]
    launch_gemm(hidden, kv_a_w, ckv, S_LEN, 576, HID);
    // 3) rmsnorm(q_a) in place
    rmsnorm_kernel<<<S_LEN, 256>>>(qa, QLR, q_a_ln, qa, QLR, QLR);
    // 4) rmsnorm(ckv[:, :512]) -> ckvn
    rmsnorm_kernel<<<S_LEN, 256>>>(ckv, 576, kv_a_ln, ckvn, KVLR, KVLR);
    // 5) rope(k_pe) -> kpe
    kpe_rope_kernel<<<(S_LEN * 32 + 255) / 256, 256>>>(ckv, pos, cosb, sinb, kpe);
    // 6) q = qa_n @ q_b_w^T               [2048,3072]
    launch_gemm(qa, q_b_w, q, S_LEN, QDIM, QLR);
    // 7) kv = ckvn @ kv_b_w^T             [2048,4096]
    launch_gemm(ckvn, kv_b_w, kv, S_LEN, KVDIM, KVLR);
    // 8) rope(q_pe) in place
    q_rope_kernel<<<(S_LEN * NH * 32 + 255) / 256, 256>>>(q, pos, cosb, sinb);
    // 9) attention -> attn                [2048,2048]
    attn_kernel<<<dim3(32, NH), 256, att_smem>>>(q, kv, kpe, attn);
    // 10) out = attn @ o_w^T              [2048,2048]
    launch_gemm(attn, o_w, out, S_LEN, HID, AODIM);
}

// round 5
// speedup vs baseline: 2.9010x; 1.2477x over previous
#include <cuda_runtime.h>
#include <cuda_bf16.h>
#include <math.h>

// Problem constants
#define S_LEN 2048
#define HID   2048
#define NH    16
#define DN    128
#define DR    64
#define DV    128
#define DQ    192      // DN + DR
#define QLR   1536
#define KVLR  512
#define QDIM  (NH * DQ)        // 3072
#define KVDIM (NH * (DN + DV)) // 4096
#define AODIM (NH * DV)        // 2048
#define SCALE 0.07216878364870323f  // 192^-0.5
#define EPSV  1e-6f

// ---------------- scratch (allocation-free: __device__ global) ----------------
#define OFF_QA    0UL
#define OFF_Q     (OFF_QA   + (size_t)S_LEN * QLR)
#define OFF_CKV   (OFF_Q    + (size_t)S_LEN * QDIM)
#define OFF_CKVN  (OFF_CKV  + (size_t)S_LEN * 576)
#define OFF_KPE   (OFF_CKVN + (size_t)S_LEN * KVLR)
#define OFF_KV    (OFF_KPE  + (size_t)S_LEN * DR)
#define OFF_ATTN  (OFF_KV   + (size_t)S_LEN * KVDIM)
// rounded (tf32-in-fp32) copies
#define OFF_HR    (OFF_ATTN + (size_t)S_LEN * AODIM)
#define OFF_W_QA  (OFF_HR   + (size_t)S_LEN * HID)
#define OFF_W_KVA (OFF_W_QA + (size_t)QLR * HID)          // padded to 640 rows
#define OFF_W_QB  (OFF_W_KVA + (size_t)640 * HID)
#define OFF_W_KVB (OFF_W_QB + (size_t)QDIM * QLR)
#define OFF_W_O   (OFF_W_KVB + (size_t)KVDIM * KVLR)
#define SCRATCH_TOTAL (OFF_W_O + (size_t)HID * AODIM)

__device__ float g_scratch[SCRATCH_TOTAL];

// ---------------- helpers ------------------------------------------------------
__device__ __forceinline__ unsigned f2tf(float x) {
    unsigned u;
    asm("cvt.rna.tf32.f32 %0, %1;" : "=r"(u) : "f"(x));
    return u;
}
__device__ __forceinline__ float rtf(float x) { return __uint_as_float(f2tf(x)); }

__device__ __forceinline__ void mma8(float* d, const unsigned* a, const unsigned* b) {
    asm volatile(
        "mma.sync.aligned.m16n8k8.row.col.f32.tf32.tf32.f32 "
        "{%0,%1,%2,%3},{%4,%5,%6,%7},{%8,%9},{%0,%1,%2,%3};\n"
        : "+f"(d[0]), "+f"(d[1]), "+f"(d[2]), "+f"(d[3])
        : "r"(a[0]), "r"(a[1]), "r"(a[2]), "r"(a[3]), "r"(b[0]), "r"(b[1]));
}

__device__ __forceinline__ void cpa16(unsigned saddr, const void* g) {
    asm volatile("cp.async.cg.shared.global [%0], [%1], 16;\n" :: "r"(saddr), "l"(g));
}
__device__ __forceinline__ void cp_commit() { asm volatile("cp.async.commit_group;\n"); }
template <int N> __device__ __forceinline__ void cp_wait() {
    asm volatile("cp.async.wait_group %0;\n" :: "n"(N));
}

// ---------------- round/copy pass: dst[i] = i<n_src ? tf32(src[i]) : 0 ---------
__global__ __launch_bounds__(256) void round_copy(
    const float4* __restrict__ src, float4* __restrict__ dst, int n4_src, int n4_dst)
{
    int i = blockIdx.x * blockDim.x + threadIdx.x;
    if (i >= n4_dst) return;
    float4 v = make_float4(0.f, 0.f, 0.f, 0.f);
    if (i < n4_src) v = src[i];
    v.x = rtf(v.x); v.y = rtf(v.y); v.z = rtf(v.z); v.w = rtf(v.w);
    dst[i] = v;
}

// ---------------- GEMM: C[M,N] = A[M,K] * W[N,K]^T, tf32, cp.async 2-stage -----
// BM=128, BN=128, BK=32, 256 threads (8 warps, 4x2), warp tile 32x64.
// Inputs A, W must be pre-rounded to tf32 (as fp32 bits). W padded so all tile
// rows are readable. K % 32 == 0, M % 128 == 0.
#define GS 36                      // smem k-stride: 36 % 8 == 4 -> conflict-free
#define STG_WORDS (2 * 128 * GS)   // A + B per stage
#define GEMM_SMEM_BYTES (2 * STG_WORDS * 4)

__device__ __forceinline__ void gemm_issue(
    const float* __restrict__ A, const float* __restrict__ W, int K,
    int m0, int n0, int k0, unsigned sa, unsigned sb, int t)
{
#pragma unroll
    for (int i = 0; i < 4; i++) {
        int id = t + 256 * i;
        int r = id >> 3, c4 = (id & 7) << 2;
        cpa16(sa + (unsigned)(r * GS + c4) * 4u, A + (size_t)(m0 + r) * K + k0 + c4);
        cpa16(sb + (unsigned)(r * GS + c4) * 4u, W + (size_t)(n0 + r) * K + k0 + c4);
    }
    cp_commit();
}

template <bool RND>
__global__ __launch_bounds__(256, 2) void gemm_tf32(
    const float* __restrict__ A, const float* __restrict__ W,
    float* __restrict__ C, int M, int N, int K)
{
    extern __shared__ unsigned sm[];

    const int t    = threadIdx.x;
    const int lane = t & 31;
    const int wid  = t >> 5;
    const int ln4  = lane >> 2;
    const int lnk  = lane & 3;
    const int warpM = wid & 3;
    const int warpN = wid >> 2;
    const int m0 = blockIdx.y * 128;
    const int n0 = blockIdx.x * 128;

    unsigned sbase = (unsigned)__cvta_generic_to_shared(sm);

    float acc[2][8][4];
#pragma unroll
    for (int mt = 0; mt < 2; mt++)
#pragma unroll
        for (int nt = 0; nt < 8; nt++)
#pragma unroll
            for (int j = 0; j < 4; j++) acc[mt][nt][j] = 0.f;

    const int nIter = K >> 5;

    // prologue: stage 0
    gemm_issue(A, W, K, m0, n0, 0,
               sbase, sbase + 128 * GS * 4, t);

    for (int it = 0; it < nIter; it++) {
        const int buf = it & 1;
        if (it + 1 < nIter) {
            const int nb = buf ^ 1;
            gemm_issue(A, W, K, m0, n0, (it + 1) << 5,
                       sbase + (unsigned)(nb * STG_WORDS) * 4u,
                       sbase + (unsigned)(nb * STG_WORDS + 128 * GS) * 4u, t);
            cp_wait<1>();
        } else {
            cp_wait<0>();
        }
        __syncthreads();

        const unsigned* As = sm + buf * STG_WORDS;
        const unsigned* Bs = As + 128 * GS;

#pragma unroll
        for (int ks = 0; ks < 4; ks++) {
            const int kk = ks * 8;
            unsigned a[2][4];
#pragma unroll
            for (int mt = 0; mt < 2; mt++) {
                const unsigned* p = As + (warpM * 32 + mt * 16 + ln4) * GS + kk + lnk;
                a[mt][0] = p[0];
                a[mt][1] = p[8 * GS];
                a[mt][2] = p[4];
                a[mt][3] = p[8 * GS + 4];
            }
#pragma unroll
            for (int nt = 0; nt < 8; nt++) {
                const unsigned* p = Bs + (warpN * 64 + nt * 8 + ln4) * GS + kk + lnk;
                unsigned b[2] = { p[0], p[4] };
#pragma unroll
                for (int mt = 0; mt < 2; mt++) mma8(acc[mt][nt], a[mt], b);
            }
        }
        __syncthreads();
    }

#pragma unroll
    for (int mt = 0; mt < 2; mt++) {
        int r0 = m0 + warpM * 32 + mt * 16 + ln4;
#pragma unroll
        for (int nt = 0; nt < 8; nt++) {
            int c = n0 + warpN * 64 + nt * 8 + 2 * lnk;
            if (c < N) {
                float v0 = acc[mt][nt][0], v1 = acc[mt][nt][1];
                float v2 = acc[mt][nt][2], v3 = acc[mt][nt][3];
                if (RND) { v0 = rtf(v0); v1 = rtf(v1); v2 = rtf(v2); v3 = rtf(v3); }
                *(float2*)(C + (size_t)r0 * N + c)       = make_float2(v0, v1);
                *(float2*)(C + (size_t)(r0 + 8) * N + c) = make_float2(v2, v3);
            }
        }
    }
}

// ---------------- RMSNorm (writes tf32-rounded) ---------------------------------
__global__ __launch_bounds__(256) void rmsnorm_kernel(
    const float* __restrict__ X, int ldx, const float* __restrict__ w,
    float* __restrict__ Y, int ldy, int n)
{
    const int row = blockIdx.x;
    const float* x = X + (size_t)row * ldx;
    float* y = Y + (size_t)row * ldy;

    float s = 0.f;
    for (int i = threadIdx.x; i < n; i += blockDim.x) { float v = x[i]; s += v * v; }

    __shared__ float red[8];
    int lane = threadIdx.x & 31, wid = threadIdx.x >> 5;
#pragma unroll
    for (int o = 16; o; o >>= 1) s += __shfl_down_sync(0xFFFFFFFFu, s, o);
    if (!lane) red[wid] = s;
    __syncthreads();
    if (wid == 0) {
        s = (lane < 8) ? red[lane] : 0.f;
#pragma unroll
        for (int o = 4; o; o >>= 1) s += __shfl_down_sync(0xFFFFFFFFu, s, o);
        if (!lane) red[0] = s;
    }
    __syncthreads();
    const float inv = rsqrtf(red[0] / (float)n + EPSV);
    for (int i = threadIdx.x; i < n; i += blockDim.x) y[i] = rtf(x[i] * inv * w[i]);
}

// ---------------- k_pe RoPE (writes rounded) ------------------------------------
__global__ __launch_bounds__(256) void kpe_rope_kernel(
    const float* __restrict__ ckv, const int* __restrict__ pos,
    const float* __restrict__ cosb, const float* __restrict__ sinb,
    float* __restrict__ kpe)
{
    int warp = (blockIdx.x * blockDim.x + threadIdx.x) >> 5;
    int lane = threadIdx.x & 31;
    if (warp >= S_LEN) return;
    int s = warp;
    int p = pos[s];
    const float* x = ckv + (size_t)s * 576 + 512;
    float x0 = x[2 * lane], x1 = x[2 * lane + 1];
    float c0 = cosb[(size_t)p * DR + lane],      s0 = sinb[(size_t)p * DR + lane];
    float c1 = cosb[(size_t)p * DR + 32 + lane], s1 = sinb[(size_t)p * DR + 32 + lane];
    kpe[(size_t)s * DR + lane]      = rtf(x0 * c0 - x1 * s0);
    kpe[(size_t)s * DR + 32 + lane] = rtf(x1 * c1 + x0 * s1);
}

// ---------------- q_pe RoPE (in place, writes rounded) --------------------------
__global__ __launch_bounds__(256) void q_rope_kernel(
    float* __restrict__ Q, const int* __restrict__ pos,
    const float* __restrict__ cosb, const float* __restrict__ sinb)
{
    int warp = (blockIdx.x * blockDim.x + threadIdx.x) >> 5;
    int lane = threadIdx.x & 31;
    if (warp >= S_LEN * NH) return;
    int s = warp >> 4, h = warp & 15;
    int p = pos[s];
    float* x = Q + (size_t)s * QDIM + h * DQ + DN;
    float x0 = x[2 * lane], x1 = x[2 * lane + 1];
    float c0 = cosb[(size_t)p * DR + lane],      s0 = sinb[(size_t)p * DR + lane];
    float c1 = cosb[(size_t)p * DR + 32 + lane], s1 = sinb[(size_t)p * DR + 32 + lane];
    float o0 = rtf(x0 * c0 - x1 * s0);
    float o1 = rtf(x1 * c1 + x0 * s1);
    __syncwarp();
    x[lane]      = o0;
    x[32 + lane] = o1;
}

// ---------------- Flash attention (causal, tf32 tensor cores) -------------------
// Inputs Q, KV, KPE pre-rounded to tf32 bits. Output written rounded.
#define QKS 196
#define VS_ 136
#define PS_ 68
#define ATT_SMEM_WORDS (2 * 64 * QKS + 64 * VS_ + 64 * PS_ + 3 * 64)

__global__ __launch_bounds__(256) void attn_kernel(
    const float* __restrict__ Q, const float* __restrict__ KV,
    const float* __restrict__ KPE, float* __restrict__ O)
{
    extern __shared__ unsigned smu[];
    unsigned* Qs = smu;
    unsigned* Ks = Qs + 64 * QKS;
    unsigned* Vs = Ks + 64 * QKS;
    unsigned* Ps = Vs + 64 * VS_;
    float* mrow = (float*)(Ps + 64 * PS_);
    float* lrow = mrow + 64;
    float* arow = lrow + 64;

    const int h  = blockIdx.y;
    const int qb = 31 - blockIdx.x;
    const int q0 = qb * 64;
    const int t    = threadIdx.x;
    const int lane = t & 31;
    const int wid  = t >> 5;
    const int ln4  = lane >> 2;
    const int lnk  = lane & 3;
    const int warpM = wid & 3;
    const int warpN = wid >> 2;

    for (int idx = t; idx < 64 * 48; idx += 256) {
        int r = idx / 48, c4 = (idx % 48) * 4;
        *(float4*)(Qs + r * QKS + c4) =
            *(const float4*)(Q + (size_t)(q0 + r) * QDIM + h * DQ + c4);
    }
    if (t < 64) { mrow[t] = -1e30f; lrow[t] = 0.f; }

    float o[8][4];
#pragma unroll
    for (int nt = 0; nt < 8; nt++)
#pragma unroll
        for (int j = 0; j < 4; j++) o[nt][j] = 0.f;
    __syncthreads();

    for (int kt = 0; kt <= qb; kt++) {
        const int k0 = kt * 64;
        for (int idx = t; idx < 64 * 48; idx += 256) {
            int r = idx / 48, c4 = (idx % 48) * 4;
            float4 v;
            if (c4 < 128) v = *(const float4*)(KV  + (size_t)(k0 + r) * KVDIM + h * 256 + c4);
            else          v = *(const float4*)(KPE + (size_t)(k0 + r) * DR + (c4 - 128));
            *(float4*)(Ks + r * QKS + c4) = v;
        }
        for (int idx = t; idx < 64 * 32; idx += 256) {
            int r = idx >> 5, c4 = (idx & 31) * 4;
            *(float4*)(Vs + r * VS_ + c4) =
                *(const float4*)(KV + (size_t)(k0 + r) * KVDIM + h * 256 + 128 + c4);
        }
        __syncthreads();

        // ---- S = Q K^T ----
        float sacc[4][4];
#pragma unroll
        for (int nt = 0; nt < 4; nt++)
#pragma unroll
            for (int j = 0; j < 4; j++) sacc[nt][j] = 0.f;

        const unsigned* qbase = Qs + (warpM * 16 + ln4) * QKS + lnk;
#pragma unroll 4
        for (int ks = 0; ks < 24; ks++) {
            const int kk = ks * 8;
            unsigned a[4];
            a[0] = qbase[kk];
            a[1] = qbase[8 * QKS + kk];
            a[2] = qbase[kk + 4];
            a[3] = qbase[8 * QKS + kk + 4];
#pragma unroll
            for (int nt = 0; nt < 4; nt++) {
                const unsigned* p = Ks + (warpN * 32 + nt * 8 + ln4) * QKS + kk + lnk;
                unsigned b[2] = { p[0], p[4] };
                mma8(sacc[nt], a, b);
            }
        }

        const bool diag = (kt == qb);
        const int rl0 = warpM * 16 + ln4;
#pragma unroll
        for (int nt = 0; nt < 4; nt++) {
            int cl = warpN * 32 + nt * 8 + 2 * lnk;
            float v0 = sacc[nt][0] * SCALE;
            float v1 = sacc[nt][1] * SCALE;
            float v2 = sacc[nt][2] * SCALE;
            float v3 = sacc[nt][3] * SCALE;
            if (diag) {
                if (cl     > rl0)     v0 = -1e30f;
                if (cl + 1 > rl0)     v1 = -1e30f;
                if (cl     > rl0 + 8) v2 = -1e30f;
                if (cl + 1 > rl0 + 8) v3 = -1e30f;
            }
            Ps[rl0 * PS_ + cl]           = __float_as_uint(v0);
            Ps[rl0 * PS_ + cl + 1]       = __float_as_uint(v1);
            Ps[(rl0 + 8) * PS_ + cl]     = __float_as_uint(v2);
            Ps[(rl0 + 8) * PS_ + cl + 1] = __float_as_uint(v3);
        }
        __syncthreads();

        // ---- online softmax: 4 threads per row ----
        {
            const int r = t >> 2, seg = t & 3;
            const float* pf = (const float*)Ps + r * PS_ + seg * 16;
            unsigned* pu = Ps + r * PS_ + seg * 16;
            float mprev = mrow[r];
            float mx = mprev;
#pragma unroll
            for (int j = 0; j < 16; j++) mx = fmaxf(mx, pf[j]);
            mx = fmaxf(mx, __shfl_xor_sync(0xFFFFFFFFu, mx, 1));
            mx = fmaxf(mx, __shfl_xor_sync(0xFFFFFFFFu, mx, 2));
            float alpha = __expf(mprev - mx);
            float s = 0.f;
#pragma unroll
            for (int j = 0; j < 16; j++) {
                float e = __expf(pf[j] - mx);
                s += e;
                pu[j] = f2tf(e);
            }
            s += __shfl_xor_sync(0xFFFFFFFFu, s, 1);
            s += __shfl_xor_sync(0xFFFFFFFFu, s, 2);
            if (seg == 0) {
                mrow[r] = mx;
                lrow[r] = lrow[r] * alpha + s;
                arow[r] = alpha;
            }
        }
        __syncthreads();

        // ---- O = O*alpha + P @ V ----
        {
            float ar0 = arow[warpM * 16 + ln4];
            float ar1 = arow[warpM * 16 + ln4 + 8];
#pragma unroll
            for (int nt = 0; nt < 8; nt++) {
                o[nt][0] *= ar0; o[nt][1] *= ar0;
                o[nt][2] *= ar1; o[nt][3] *= ar1;
            }
            const unsigned* pbase = Ps + (warpM * 16 + ln4) * PS_ + lnk;
#pragma unroll
            for (int ks = 0; ks < 8; ks++) {
                const int kk = ks * 8;
                unsigned a[4];
                a[0] = pbase[kk];
                a[1] = pbase[8 * PS_ + kk];
                a[2] = pbase[kk + 4];
                a[3] = pbase[8 * PS_ + kk + 4];
#pragma unroll
                for (int nt = 0; nt < 8; nt++) {
                    const unsigned* p = Vs + (kk + lnk) * VS_ + warpN * 64 + nt * 8 + ln4;
                    unsigned b[2] = { p[0], p[4 * VS_] };
                    mma8(o[nt], a, b);
                }
            }
        }
        __syncthreads();
    }

    {
        float inv0 = 1.f / lrow[warpM * 16 + ln4];
        float inv1 = 1.f / lrow[warpM * 16 + ln4 + 8];
        int r0 = q0 + warpM * 16 + ln4;
#pragma unroll
        for (int nt = 0; nt < 8; nt++) {
            int c = warpN * 64 + nt * 8 + 2 * lnk;
            float* dst0 = O + (size_t)r0 * AODIM + h * DV + c;
            float* dst1 = O + (size_t)(r0 + 8) * AODIM + h * DV + c;
            *(float2*)dst0 = make_float2(rtf(o[nt][0] * inv0), rtf(o[nt][1] * inv0));
            *(float2*)dst1 = make_float2(rtf(o[nt][2] * inv1), rtf(o[nt][3] * inv1));
        }
    }
}

// ---------------- host launcher --------------------------------------------------
template <bool RND>
static inline void launch_gemm(const float* A, const float* W, float* C,
                               int M, int N, int K) {
    dim3 grid((N + 127) / 128, M / 128);
    gemm_tf32<RND><<<grid, 256, GEMM_SMEM_BYTES>>>(A, W, C, M, N, K);
}

static inline void launch_round(const float* src, float* dst, size_t n_src, size_t n_dst) {
    int n4s = (int)(n_src / 4), n4d = (int)(n_dst / 4);
    round_copy<<<(n4d + 255) / 256, 256>>>((const float4*)src, (float4*)dst, n4s, n4d);
}

extern "C" void kernel_launch(void* const* d_in, const int* in_sizes, int n_in,
                              void* d_out, int out_size)
{
    const float* hidden  = (const float*)d_in[0];
    const float* q_a_w   = (const float*)d_in[1];
    const float* q_a_ln  = (const float*)d_in[2];
    const float* q_b_w   = (const float*)d_in[3];
    const float* kv_a_w  = (const float*)d_in[4];
    const float* kv_a_ln = (const float*)d_in[5];
    const float* kv_b_w  = (const float*)d_in[6];
    const float* o_w     = (const float*)d_in[7];
    const float* cosb    = (const float*)d_in[8];
    const float* sinb    = (const float*)d_in[9];
    // d_in[10] = attention_mask (causal triu; semantics reproduced directly)
    const int*   pos     = (const int*)d_in[11];
    float* out = (float*)d_out;

    float* base;
    cudaGetSymbolAddress((void**)&base, g_scratch);
    float* qa    = base + OFF_QA;
    float* q     = base + OFF_Q;
    float* ckv   = base + OFF_CKV;
    float* ckvn  = base + OFF_CKVN;
    float* kpe   = base + OFF_KPE;
    float* kv    = base + OFF_KV;
    float* attn  = base + OFF_ATTN;
    float* hr    = base + OFF_HR;
    float* w_qa  = base + OFF_W_QA;
    float* w_kva = base + OFF_W_KVA;
    float* w_qb  = base + OFF_W_QB;
    float* w_kvb = base + OFF_W_KVB;
    float* w_o   = base + OFF_W_O;

    cudaFuncSetAttribute(attn_kernel, cudaFuncAttributeMaxDynamicSharedMemorySize,
                         ATT_SMEM_WORDS * 4);
    cudaFuncSetAttribute(gemm_tf32<true>, cudaFuncAttributeMaxDynamicSharedMemorySize,
                         GEMM_SMEM_BYTES);
    cudaFuncSetAttribute(gemm_tf32<false>, cudaFuncAttributeMaxDynamicSharedMemorySize,
                         GEMM_SMEM_BYTES);

    // 0) round inputs/weights to tf32 bit patterns (kv_a_w padded 576 -> 640 rows)
    launch_round(hidden, hr,    (size_t)S_LEN * HID, (size_t)S_LEN * HID);
    launch_round(q_a_w,  w_qa,  (size_t)QLR * HID,   (size_t)QLR * HID);
    launch_round(kv_a_w, w_kva, (size_t)576 * HID,   (size_t)640 * HID);
    launch_round(q_b_w,  w_qb,  (size_t)QDIM * QLR,  (size_t)QDIM * QLR);
    launch_round(kv_b_w, w_kvb, (size_t)KVDIM * KVLR,(size_t)KVDIM * KVLR);
    launch_round(o_w,    w_o,   (size_t)HID * AODIM, (size_t)HID * AODIM);

    // 1) q_a = hidden @ q_a_w^T           [2048,1536]
    launch_gemm<true>(hr, w_qa, qa, S_LEN, QLR, HID);
    // 2) ckv = hidden @ kv_a_w^T          [2048,576]
    launch_gemm<true>(hr, w_kva, ckv, S_LEN, 576, HID);
    // 3) rmsnorm(q_a) in place
    rmsnorm_kernel<<<S_LEN, 256>>>(qa, QLR, q_a_ln, qa, QLR, QLR);
    // 4) rmsnorm(ckv[:, :512]) -> ckvn
    rmsnorm_kernel<<<S_LEN, 256>>>(ckv, 576, kv_a_ln, ckvn, KVLR, KVLR);
    // 5) rope(k_pe) -> kpe
    kpe_rope_kernel<<<(S_LEN * 32 + 255) / 256, 256>>>(ckv, pos, cosb, sinb, kpe);
    // 6) q = qa_n @ q_b_w^T               [2048,3072]
    launch_gemm<true>(qa, w_qb, q, S_LEN, QDIM, QLR);
    // 7) kv = ckvn @ kv_b_w^T             [2048,4096]
    launch_gemm<true>(ckvn, w_kvb, kv, S_LEN, KVDIM, KVLR);
    // 8) rope(q_pe) in place
    q_rope_kernel<<<(S_LEN * NH * 32 + 255) / 256, 256>>>(q, pos, cosb, sinb);
    // 9) attention -> attn                [2048,2048]
    attn_kernel<<<dim3(32, NH), 256, ATT_SMEM_WORDS * 4>>>(q, kv, kpe, attn);
    // 10) out = attn @ o_w^T              [2048,2048]
    launch_gemm<false>(attn, w_o, out, S_LEN, HID, AODIM);
}

// round 7
// speedup vs baseline: 3.3295x; 1.1477x over previous
#include <cuda_runtime.h>
#include <cuda_bf16.h>
#include <math.h>

// Problem constants
#define S_LEN 2048
#define HID   2048
#define NH    16
#define DN    128
#define DR    64
#define DV    128
#define DQ    192      // DN + DR
#define QLR   1536
#define KVLR  512
#define QDIM  (NH * DQ)        // 3072
#define KVDIM (NH * (DN + DV)) // 4096
#define AODIM (NH * DV)        // 2048
#define SCALE 0.07216878364870323f  // 192^-0.5
#define EPSV  1e-6f

// ---------------- scratch (allocation-free: __device__ global) ----------------
#define OFF_QA    0UL
#define OFF_Q     (OFF_QA   + (size_t)S_LEN * QLR)
#define OFF_CKV   (OFF_Q    + (size_t)S_LEN * QDIM)
#define OFF_CKVN  (OFF_CKV  + (size_t)S_LEN * 576)
#define OFF_KPE   (OFF_CKVN + (size_t)S_LEN * KVLR)
#define OFF_KV    (OFF_KPE  + (size_t)S_LEN * DR)
#define OFF_ATTN  (OFF_KV   + (size_t)S_LEN * KVDIM)
// rounded (tf32-in-fp32) copies
#define OFF_HR    (OFF_ATTN + (size_t)S_LEN * AODIM)
#define OFF_W_QA  (OFF_HR   + (size_t)S_LEN * HID)
#define OFF_W_KVA (OFF_W_QA + (size_t)QLR * HID)          // padded to 640 rows
#define OFF_W_QB  (OFF_W_KVA + (size_t)640 * HID)
#define OFF_W_KVB (OFF_W_QB + (size_t)QDIM * QLR)
#define OFF_W_O   (OFF_W_KVB + (size_t)KVDIM * KVLR)
#define SCRATCH_TOTAL (OFF_W_O + (size_t)HID * AODIM)

__device__ float g_scratch[SCRATCH_TOTAL];

// ---------------- helpers ------------------------------------------------------
__device__ __forceinline__ unsigned f2tf(float x) {
    unsigned u;
    asm("cvt.rna.tf32.f32 %0, %1;" : "=r"(u) : "f"(x));
    return u;
}
__device__ __forceinline__ float rtf(float x) { return __uint_as_float(f2tf(x)); }

__device__ __forceinline__ void mma8(float* d, const unsigned* a, const unsigned* b) {
    asm volatile(
        "mma.sync.aligned.m16n8k8.row.col.f32.tf32.tf32.f32 "
        "{%0,%1,%2,%3},{%4,%5,%6,%7},{%8,%9},{%0,%1,%2,%3};\n"
        : "+f"(d[0]), "+f"(d[1]), "+f"(d[2]), "+f"(d[3])
        : "r"(a[0]), "r"(a[1]), "r"(a[2]), "r"(a[3]), "r"(b[0]), "r"(b[1]));
}

__device__ __forceinline__ void cpa16(unsigned saddr, const void* g) {
    asm volatile("cp.async.cg.shared.global [%0], [%1], 16;\n" :: "r"(saddr), "l"(g));
}
__device__ __forceinline__ void cp_commit() { asm volatile("cp.async.commit_group;\n"); }
template <int N> __device__ __forceinline__ void cp_wait() {
    asm volatile("cp.async.wait_group %0;\n" :: "n"(N));
}

// ---------------- round/copy pass: dst[i] = i<n_src ? tf32(src[i]) : 0 ---------
__global__ __launch_bounds__(256) void round_copy(
    const float4* __restrict__ src, float4* __restrict__ dst, int n4_src, int n4_dst)
{
    int i = blockIdx.x * blockDim.x + threadIdx.x;
    if (i >= n4_dst) return;
    float4 v = make_float4(0.f, 0.f, 0.f, 0.f);
    if (i < n4_src) v = src[i];
    v.x = rtf(v.x); v.y = rtf(v.y); v.z = rtf(v.z); v.w = rtf(v.w);
    dst[i] = v;
}

// ---------------- GEMM: C[M,N] = A[M,K] * W[N,K]^T, tf32, cp.async 2-stage -----
// BM=128, BN=128, BK=32, 256 threads (8 warps, 4x2), warp tile 32x64.
// Inputs A, W pre-rounded tf32 (fp32 bits). W row-padded. K%32==0, M%128==0.
#define GS 36                      // smem k-stride: 36 % 8 == 4 -> conflict-free
#define STG_WORDS (2 * 128 * GS)   // A + B per stage
#define GEMM_SMEM_BYTES (2 * STG_WORDS * 4)

__device__ __forceinline__ void gemm_issue(
    const float* __restrict__ A, const float* __restrict__ W, int K,
    int m0, int n0, int k0, unsigned sa, unsigned sb, int t)
{
#pragma unroll
    for (int i = 0; i < 4; i++) {
        int id = t + 256 * i;
        int r = id >> 3, c4 = (id & 7) << 2;
        cpa16(sa + (unsigned)(r * GS + c4) * 4u, A + (size_t)(m0 + r) * K + k0 + c4);
        cpa16(sb + (unsigned)(r * GS + c4) * 4u, W + (size_t)(n0 + r) * K + k0 + c4);
    }
    cp_commit();
}

template <bool RND>
__global__ __launch_bounds__(256, 2) void gemm_tf32(
    const float* __restrict__ A, const float* __restrict__ W,
    float* __restrict__ C, int M, int N, int K)
{
    extern __shared__ unsigned sm[];

    const int t    = threadIdx.x;
    const int lane = t & 31;
    const int wid  = t >> 5;
    const int ln4  = lane >> 2;
    const int lnk  = lane & 3;
    const int warpM = wid & 3;
    const int warpN = wid >> 2;
    const int m0 = blockIdx.y * 128;
    const int n0 = blockIdx.x * 128;

    unsigned sbase = (unsigned)__cvta_generic_to_shared(sm);

    float acc[2][8][4];
#pragma unroll
    for (int mt = 0; mt < 2; mt++)
#pragma unroll
        for (int nt = 0; nt < 8; nt++)
#pragma unroll
            for (int j = 0; j < 4; j++) acc[mt][nt][j] = 0.f;

    const int nIter = K >> 5;

    // prologue: stage 0
    gemm_issue(A, W, K, m0, n0, 0, sbase, sbase + 128 * GS * 4, t);

    for (int it = 0; it < nIter; it++) {
        const int buf = it & 1;
        if (it + 1 < nIter) {
            const int nb = buf ^ 1;
            gemm_issue(A, W, K, m0, n0, (it + 1) << 5,
                       sbase + (unsigned)(nb * STG_WORDS) * 4u,
                       sbase + (unsigned)(nb * STG_WORDS + 128 * GS) * 4u, t);
            cp_wait<1>();
        } else {
            cp_wait<0>();
        }
        __syncthreads();

        const unsigned* As = sm + buf * STG_WORDS;
        const unsigned* Bs = As + 128 * GS;

#pragma unroll
        for (int ks = 0; ks < 4; ks++) {
            const int kk = ks * 8;
            unsigned a[2][4];
#pragma unroll
            for (int mt = 0; mt < 2; mt++) {
                const unsigned* p = As + (warpM * 32 + mt * 16 + ln4) * GS + kk + lnk;
                a[mt][0] = p[0];
                a[mt][1] = p[8 * GS];
                a[mt][2] = p[4];
                a[mt][3] = p[8 * GS + 4];
            }
#pragma unroll
            for (int nt = 0; nt < 8; nt++) {
                const unsigned* p = Bs + (warpN * 64 + nt * 8 + ln4) * GS + kk + lnk;
                unsigned b[2] = { p[0], p[4] };
#pragma unroll
                for (int mt = 0; mt < 2; mt++) mma8(acc[mt][nt], a[mt], b);
            }
        }
        __syncthreads();
    }

#pragma unroll
    for (int mt = 0; mt < 2; mt++) {
        int r0 = m0 + warpM * 32 + mt * 16 + ln4;
#pragma unroll
        for (int nt = 0; nt < 8; nt++) {
            int c = n0 + warpN * 64 + nt * 8 + 2 * lnk;
            if (c < N) {
                float v0 = acc[mt][nt][0], v1 = acc[mt][nt][1];
                float v2 = acc[mt][nt][2], v3 = acc[mt][nt][3];
                if (RND) { v0 = rtf(v0); v1 = rtf(v1); v2 = rtf(v2); v3 = rtf(v3); }
                *(float2*)(C + (size_t)r0 * N + c)       = make_float2(v0, v1);
                *(float2*)(C + (size_t)(r0 + 8) * N + c) = make_float2(v2, v3);
            }
        }
    }
}

// ---------------- RMSNorm (writes tf32-rounded) ---------------------------------
__global__ __launch_bounds__(256) void rmsnorm_kernel(
    const float* __restrict__ X, int ldx, const float* __restrict__ w,
    float* __restrict__ Y, int ldy, int n)
{
    const int row = blockIdx.x;
    const float* x = X + (size_t)row * ldx;
    float* y = Y + (size_t)row * ldy;

    float s = 0.f;
    for (int i = threadIdx.x; i < n; i += blockDim.x) { float v = x[i]; s += v * v; }

    __shared__ float red[8];
    int lane = threadIdx.x & 31, wid = threadIdx.x >> 5;
#pragma unroll
    for (int o = 16; o; o >>= 1) s += __shfl_down_sync(0xFFFFFFFFu, s, o);
    if (!lane) red[wid] = s;
    __syncthreads();
    if (wid == 0) {
        s = (lane < 8) ? red[lane] : 0.f;
#pragma unroll
        for (int o = 4; o; o >>= 1) s += __shfl_down_sync(0xFFFFFFFFu, s, o);
        if (!lane) red[0] = s;
    }
    __syncthreads();
    const float inv = rsqrtf(red[0] / (float)n + EPSV);
    for (int i = threadIdx.x; i < n; i += blockDim.x) y[i] = rtf(x[i] * inv * w[i]);
}

// ---------------- k_pe RoPE (writes rounded) ------------------------------------
__global__ __launch_bounds__(256) void kpe_rope_kernel(
    const float* __restrict__ ckv, const int* __restrict__ pos,
    const float* __restrict__ cosb, const float* __restrict__ sinb,
    float* __restrict__ kpe)
{
    int warp = (blockIdx.x * blockDim.x + threadIdx.x) >> 5;
    int lane = threadIdx.x & 31;
    if (warp >= S_LEN) return;
    int s = warp;
    int p = pos[s];
    const float* x = ckv + (size_t)s * 576 + 512;
    float x0 = x[2 * lane], x1 = x[2 * lane + 1];
    float c0 = cosb[(size_t)p * DR + lane],      s0 = sinb[(size_t)p * DR + lane];
    float c1 = cosb[(size_t)p * DR + 32 + lane], s1 = sinb[(size_t)p * DR + 32 + lane];
    kpe[(size_t)s * DR + lane]      = rtf(x0 * c0 - x1 * s0);
    kpe[(size_t)s * DR + 32 + lane] = rtf(x1 * c1 + x0 * s1);
}

// ---------------- q_pe RoPE (in place, writes rounded) --------------------------
__global__ __launch_bounds__(256) void q_rope_kernel(
    float* __restrict__ Q, const int* __restrict__ pos,
    const float* __restrict__ cosb, const float* __restrict__ sinb)
{
    int warp = (blockIdx.x * blockDim.x + threadIdx.x) >> 5;
    int lane = threadIdx.x & 31;
    if (warp >= S_LEN * NH) return;
    int s = warp >> 4, h = warp & 15;
    int p = pos[s];
    float* x = Q + (size_t)s * QDIM + h * DQ + DN;
    float x0 = x[2 * lane], x1 = x[2 * lane + 1];
    float c0 = cosb[(size_t)p * DR + lane],      s0 = sinb[(size_t)p * DR + lane];
    float c1 = cosb[(size_t)p * DR + 32 + lane], s1 = sinb[(size_t)p * DR + 32 + lane];
    float o0 = rtf(x0 * c0 - x1 * s0);
    float o1 = rtf(x1 * c1 + x0 * s1);
    __syncwarp();
    x[lane]      = o0;
    x[32 + lane] = o1;
}

// ---------------- Flash attention (causal, tf32 mma.sync) -----------------------
// Inputs Q, KV, KPE pre-rounded to tf32 bits. Output written rounded.
#define QKS 196
#define VS_ 136
#define PS_ 68
#define ATT_SMEM_WORDS (2 * 64 * QKS + 64 * VS_ + 64 * PS_ + 3 * 64)

__global__ __launch_bounds__(256) void attn_kernel(
    const float* __restrict__ Q, const float* __restrict__ KV,
    const float* __restrict__ KPE, float* __restrict__ O)
{
    extern __shared__ unsigned smu[];
    unsigned* Qs = smu;
    unsigned* Ks = Qs + 64 * QKS;
    unsigned* Vs = Ks + 64 * QKS;
    unsigned* Ps = Vs + 64 * VS_;
    float* mrow = (float*)(Ps + 64 * PS_);
    float* lrow = mrow + 64;
    float* arow = lrow + 64;

    const int h  = blockIdx.y;
    const int qb = 31 - blockIdx.x;
    const int q0 = qb * 64;
    const int t    = threadIdx.x;
    const int lane = t & 31;
    const int wid  = t >> 5;
    const int ln4  = lane >> 2;
    const int lnk  = lane & 3;
    const int warpM = wid & 3;
    const int warpN = wid >> 2;

    const float* KVh = KV + h * 256;

    for (int idx = t; idx < 64 * 48; idx += 256) {
        int r = idx / 48, c4 = (idx % 48) * 4;
        *(float4*)(Qs + r * QKS + c4) =
            *(const float4*)(Q + (size_t)(q0 + r) * QDIM + h * DQ + c4);
    }
    if (t < 64) { mrow[t] = -1e30f; lrow[t] = 0.f; }

    float o[8][4];
#pragma unroll
    for (int nt = 0; nt < 8; nt++)
#pragma unroll
        for (int j = 0; j < 4; j++) o[nt][j] = 0.f;
    __syncthreads();

    for (int kt = 0; kt <= qb; kt++) {
        const int k0 = kt * 64;
        // fused K-nope + V load: one coalesced sweep of 64 float4 per kv row
#pragma unroll
        for (int i = 0; i < 16; i++) {
            int idx = t + 256 * i;            // 0 .. 4095
            int r = idx >> 6, c4 = (idx & 63) << 2;
            float4 v = *(const float4*)(KVh + (size_t)(k0 + r) * KVDIM + c4);
            if (c4 < 128) *(float4*)(Ks + r * QKS + c4)         = v;
            else          *(float4*)(Vs + r * VS_ + (c4 - 128)) = v;
        }
        // kpe -> Ks cols 128..191
#pragma unroll
        for (int i = 0; i < 4; i++) {
            int idx = t + 256 * i;            // 0 .. 1023
            int r = idx >> 4, c4 = (idx & 15) << 2;
            *(float4*)(Ks + r * QKS + 128 + c4) =
                *(const float4*)(KPE + (size_t)(k0 + r) * DR + c4);
        }
        __syncthreads();

        // ---- S = Q K^T ----
        float sacc[4][4];
#pragma unroll
        for (int nt = 0; nt < 4; nt++)
#pragma unroll
            for (int j = 0; j < 4; j++) sacc[nt][j] = 0.f;

        const unsigned* qbase = Qs + (warpM * 16 + ln4) * QKS + lnk;
#pragma unroll 4
        for (int ks = 0; ks < 24; ks++) {
            const int kk = ks * 8;
            unsigned a[4];
            a[0] = qbase[kk];
            a[1] = qbase[8 * QKS + kk];
            a[2] = qbase[kk + 4];
            a[3] = qbase[8 * QKS + kk + 4];
#pragma unroll
            for (int nt = 0; nt < 4; nt++) {
                const unsigned* p = Ks + (warpN * 32 + nt * 8 + ln4) * QKS + kk + lnk;
                unsigned b[2] = { p[0], p[4] };
                mma8(sacc[nt], a, b);
            }
        }

        const bool diag = (kt == qb);
        const int rl0 = warpM * 16 + ln4;
#pragma unroll
        for (int nt = 0; nt < 4; nt++) {
            int cl = warpN * 32 + nt * 8 + 2 * lnk;
            float v0 = sacc[nt][0] * SCALE;
            float v1 = sacc[nt][1] * SCALE;
            float v2 = sacc[nt][2] * SCALE;
            float v3 = sacc[nt][3] * SCALE;
            if (diag) {
                if (cl     > rl0)     v0 = -1e30f;
                if (cl + 1 > rl0)     v1 = -1e30f;
                if (cl     > rl0 + 8) v2 = -1e30f;
                if (cl + 1 > rl0 + 8) v3 = -1e30f;
            }
            Ps[rl0 * PS_ + cl]           = __float_as_uint(v0);
            Ps[rl0 * PS_ + cl + 1]       = __float_as_uint(v1);
            Ps[(rl0 + 8) * PS_ + cl]     = __float_as_uint(v2);
            Ps[(rl0 + 8) * PS_ + cl + 1] = __float_as_uint(v3);
        }
        __syncthreads();

        // ---- online softmax: 4 threads per row ----
        {
            const int r = t >> 2, seg = t & 3;
            const float* pf = (const float*)Ps + r * PS_ + seg * 16;
            unsigned* pu = Ps + r * PS_ + seg * 16;
            float mprev = mrow[r];
            float mx = mprev;
#pragma unroll
            for (int j = 0; j < 16; j++) mx = fmaxf(mx, pf[j]);
            mx = fmaxf(mx, __shfl_xor_sync(0xFFFFFFFFu, mx, 1));
            mx = fmaxf(mx, __shfl_xor_sync(0xFFFFFFFFu, mx, 2));
            float alpha = __expf(mprev - mx);
            float s = 0.f;
#pragma unroll
            for (int j = 0; j < 16; j++) {
                float e = __expf(pf[j] - mx);
                s += e;
                pu[j] = f2tf(e);
            }
            s += __shfl_xor_sync(0xFFFFFFFFu, s, 1);
            s += __shfl_xor_sync(0xFFFFFFFFu, s, 2);
            if (seg == 0) {
                mrow[r] = mx;
                lrow[r] = lrow[r] * alpha + s;
                arow[r] = alpha;
            }
        }
        __syncthreads();

        // ---- O = O*alpha + P @ V ----
        {
            float ar0 = arow[warpM * 16 + ln4];
            float ar1 = arow[warpM * 16 + ln4 + 8];
#pragma unroll
            for (int nt = 0; nt < 8; nt++) {
                o[nt][0] *= ar0; o[nt][1] *= ar0;
                o[nt][2] *= ar1; o[nt][3] *= ar1;
            }
            const unsigned* pbase = Ps + (warpM * 16 + ln4) * PS_ + lnk;
#pragma unroll
            for (int ks = 0; ks < 8; ks++) {
                const int kk = ks * 8;
                unsigned a[4];
                a[0] = pbase[kk];
                a[1] = pbase[8 * PS_ + kk];
                a[2] = pbase[kk + 4];
                a[3] = pbase[8 * PS_ + kk + 4];
#pragma unroll
                for (int nt = 0; nt < 8; nt++) {
                    const unsigned* p = Vs + (kk + lnk) * VS_ + warpN * 64 + nt * 8 + ln4;
                    unsigned b[2] = { p[0], p[4 * VS_] };
                    mma8(o[nt], a, b);
                }
            }
        }
        __syncthreads();
    }

    {
        float inv0 = 1.f / lrow[warpM * 16 + ln4];
        float inv1 = 1.f / lrow[warpM * 16 + ln4 + 8];
        int r0 = q0 + warpM * 16 + ln4;
#pragma unroll
        for (int nt = 0; nt < 8; nt++) {
            int c = warpN * 64 + nt * 8 + 2 * lnk;
            float* dst0 = O + (size_t)r0 * AODIM + h * DV + c;
            float* dst1 = O + (size_t)(r0 + 8) * AODIM + h * DV + c;
            *(float2*)dst0 = make_float2(rtf(o[nt][0] * inv0), rtf(o[nt][1] * inv0));
            *(float2*)dst1 = make_float2(rtf(o[nt][2] * inv1), rtf(o[nt][3] * inv1));
        }
    }
}

// ---------------- host launcher ---------------------------------------------------
template <bool RND>
static inline void launch_gemm(const float* A, const float* W, float* C,
                               int M, int N, int K) {
    dim3 grid((N + 127) / 128, M / 128);
    gemm_tf32<RND><<<grid, 256, GEMM_SMEM_BYTES>>>(A, W, C, M, N, K);
}

static inline void launch_round(const float* src, float* dst, size_t n_src, size_t n_dst) {
    int n4s = (int)(n_src / 4), n4d = (int)(n_dst / 4);
    round_copy<<<(n4d + 255) / 256, 256>>>((const float4*)src, (float4*)dst, n4s, n4d);
}

extern "C" void kernel_launch(void* const* d_in, const int* in_sizes, int n_in,
                              void* d_out, int out_size)
{
    const float* hidden  = (const float*)d_in[0];
    const float* q_a_w   = (const float*)d_in[1];
    const float* q_a_ln  = (const float*)d_in[2];
    const float* q_b_w   = (const float*)d_in[3];
    const float* kv_a_w  = (const float*)d_in[4];
    const float* kv_a_ln = (const float*)d_in[5];
    const float* kv_b_w  = (const float*)d_in[6];
    const float* o_w     = (const float*)d_in[7];
    const float* cosb    = (const float*)d_in[8];
    const float* sinb    = (const float*)d_in[9];
    // d_in[10] = attention_mask (causal triu; semantics reproduced directly)
    const int*   pos     = (const int*)d_in[11];
    float* out = (float*)d_out;

    float* base;
    cudaGetSymbolAddress((void**)&base, g_scratch);
    float* qa    = base + OFF_QA;
    float* q     = base + OFF_Q;
    float* ckv   = base + OFF_CKV;
    float* ckvn  = base + OFF_CKVN;
    float* kpe   = base + OFF_KPE;
    float* kv    = base + OFF_KV;
    float* attn  = base + OFF_ATTN;
    float* hr    = base + OFF_HR;
    float* w_qa  = base + OFF_W_QA;
    float* w_kva = base + OFF_W_KVA;
    float* w_qb  = base + OFF_W_QB;
    float* w_kvb = base + OFF_W_KVB;
    float* w_o   = base + OFF_W_O;

    cudaFuncSetAttribute(attn_kernel, cudaFuncAttributeMaxDynamicSharedMemorySize,
                         ATT_SMEM_WORDS * 4);
    cudaFuncSetAttribute(gemm_tf32<true>, cudaFuncAttributeMaxDynamicSharedMemorySize,
                         GEMM_SMEM_BYTES);
    cudaFuncSetAttribute(gemm_tf32<false>, cudaFuncAttributeMaxDynamicSharedMemorySize,
                         GEMM_SMEM_BYTES);

    // 0) round inputs/weights (5 launches; o_w is rounded later so that the
    //    6th launch overall is the q_a GEMM -> ncu -s 5 -c 1 profiles it)
    launch_round(hidden, hr,    (size_t)S_LEN * HID, (size_t)S_LEN * HID);
    launch_round(q_a_w,  w_qa,  (size_t)QLR * HID,   (size_t)QLR * HID);
    launch_round(kv_a_w, w_kva, (size_t)576 * HID,   (size_t)640 * HID);
    launch_round(q_b_w,  w_qb,  (size_t)QDIM * QLR,  (size_t)QDIM * QLR);
    launch_round(kv_b_w, w_kvb, (size_t)KVDIM * KVLR,(size_t)KVDIM * KVLR);

    // 1) q_a = hidden @ q_a_w^T           [2048,1536]   <-- launch #6 (profiled)
    launch_gemm<true>(hr, w_qa, qa, S_LEN, QLR, HID);
    // 2) ckv = hidden @ kv_a_w^T          [2048,576]
    launch_gemm<true>(hr, w_kva, ckv, S_LEN, 576, HID);
    // 3) rmsnorm(q_a) in place
    rmsnorm_kernel<<<S_LEN, 256>>>(qa, QLR, q_a_ln, qa, QLR, QLR);
    // 4) rmsnorm(ckv[:, :512]) -> ckvn
    rmsnorm_kernel<<<S_LEN, 256>>>(ckv, 576, kv_a_ln, ckvn, KVLR, KVLR);
    // 5) rope(k_pe) -> kpe
    kpe_rope_kernel<<<(S_LEN * 32 + 255) / 256, 256>>>(ckv, pos, cosb, sinb, kpe);
    // 6) q = qa_n @ q_b_w^T               [2048,3072]
    launch_gemm<true>(qa, w_qb, q, S_LEN, QDIM, QLR);
    // 7) kv = ckvn @ kv_b_w^T             [2048,4096]
    launch_gemm<true>(ckvn, w_kvb, kv, S_LEN, KVDIM, KVLR);
    // 8) rope(q_pe) in place
    q_rope_kernel<<<(S_LEN * NH * 32 + 255) / 256, 256>>>(q, pos, cosb, sinb);
    // 9) attention -> attn                [2048,2048]
    attn_kernel<<<dim3(32, NH), 256, ATT_SMEM_WORDS * 4>>>(q, kv, kpe, attn);
    // 10) round o_w (independent; moved here to keep GEMM at launch #6)
    launch_round(o_w, w_o, (size_t)HID * AODIM, (size_t)HID * AODIM);
    // 11) out = attn @ o_w^T              [2048,2048]
    launch_gemm<false>(attn, w_o, out, S_LEN, HID, AODIM);
}